// round 1
// baseline (speedup 1.0000x reference)
#include <cuda_runtime.h>

// Dilated attention, fused over all 4 rates.
// B=4, H=16, T=8192, D=64. One block per (b, h, 64-token window).
// Window decomposition per head h, window w:
//   r=1: S=8,  warp j active iff j%2==h%2,            k0=8j
//   r=2: S=16, seg j2=wid>>1 active iff j2==h%4,      k0=16*j2
//   r=3: S=32, seg j3=wid>>2 active iff (2w+j3)%8==h%8, k0=32*j3
//   r=4: S=64, active iff w%16==h%16,                 k0=0
// Each warp owns 8 query rows (rows 8*wid .. 8*wid+7).
// Lane layout: i = lane>>2 (row in warp), kk = lane&3 (key slot / d-quarter).

#define STRIDE  68   // smem row stride (floats) for 64-wide tiles, conflict-free
#define PSTRIDE 66   // smem stride for prob rows, conflict-free broadcast reads

__device__ __forceinline__ float dot4(float4 a, float4 b) {
    return a.x * b.x + a.y * b.y + a.z * b.z + a.w * b.w;
}

// One segment-attention for this warp's 8 rows. KMAX = 4*NB keys (>= all
// causally-valid keys for the warp's rows). Probs for masked keys become 0.
template <int NB>
__device__ __forceinline__ void seg_attn(
    const float* __restrict__ qs, const float* __restrict__ ks,
    const float* __restrict__ vs, float* __restrict__ ps,
    int w_id, int lane, int k0, float* acc)
{
    const int i  = lane >> 2;
    const int kk = lane & 3;
    const int qr = (w_id << 3) + i;           // query row within window
    const float* qrow  = qs + qr * STRIDE;
    const float* kbase = ks + (k0 + kk) * STRIDE;

    // ---- scores: each lane computes NB dots (keys k0+kk, k0+kk+4, ...) ----
    float sc[NB];
#pragma unroll
    for (int kb = 0; kb < NB; kb++) sc[kb] = 0.f;
#pragma unroll 4
    for (int dc = 0; dc < 16; dc++) {
        float4 qv = *reinterpret_cast<const float4*>(qrow + dc * 4);
#pragma unroll
        for (int kb = 0; kb < NB; kb++) {
            float4 kv = *reinterpret_cast<const float4*>(kbase + kb * 4 * STRIDE + dc * 4);
            sc[kb] += dot4(qv, kv);
        }
    }

    // ---- causal mask + scale + softmax (4-lane groups share a row) ----
    float m = -1e30f;
#pragma unroll
    for (int kb = 0; kb < NB; kb++) {
        int key = k0 + kb * 4 + kk;
        sc[kb] = (key <= qr) ? sc[kb] * 0.125f : -1e30f;
        m = fmaxf(m, sc[kb]);
    }
    m = fmaxf(m, __shfl_xor_sync(0xffffffffu, m, 1));
    m = fmaxf(m, __shfl_xor_sync(0xffffffffu, m, 2));
    float sum = 0.f;
#pragma unroll
    for (int kb = 0; kb < NB; kb++) { sc[kb] = __expf(sc[kb] - m); sum += sc[kb]; }
    sum += __shfl_xor_sync(0xffffffffu, sum, 1);
    sum += __shfl_xor_sync(0xffffffffu, sum, 2);
    float inv = 1.f / sum;

    // stash normalized probs in smem so the PV loop needs no reg-indexed array
    float* prow = ps + (w_id * 8 + i) * PSTRIDE;
#pragma unroll
    for (int kb = 0; kb < NB; kb++) prow[kb * 4 + kk] = sc[kb] * inv;
    __syncwarp();

    // ---- PV: lane accumulates its d-quarter of its row over all keys ----
    const int dq = kk << 4;
    const float* vbase = vs + k0 * STRIDE + dq;
#pragma unroll 4
    for (int c = 0; c < NB * 4; c++) {
        float p = prow[c];
        const float* vr = vbase + c * STRIDE;
#pragma unroll
        for (int j = 0; j < 4; j++) {
            float4 vv = *reinterpret_cast<const float4*>(vr + j * 4);
            acc[j * 4 + 0] += p * vv.x;
            acc[j * 4 + 1] += p * vv.y;
            acc[j * 4 + 2] += p * vv.z;
            acc[j * 4 + 3] += p * vv.w;
        }
    }
    __syncwarp();   // protect prow before the next rate overwrites it
}

#define SMEM_KS (64 * STRIDE)
#define SMEM_VS (2 * 64 * STRIDE)
#define SMEM_PS (3 * 64 * STRIDE)
#define SMEM_FLOATS (3 * 64 * STRIDE + 64 * PSTRIDE)
#define SMEM_BYTES  (SMEM_FLOATS * 4)

__global__ void __launch_bounds__(256, 3)
dilated_attn_kernel(const float* __restrict__ Q, const float* __restrict__ K,
                    const float* __restrict__ V, float* __restrict__ out)
{
    extern __shared__ float smem[];
    float* qs = smem;
    float* ks = smem + SMEM_KS;
    float* vs = smem + SMEM_VS;
    float* ps = smem + SMEM_PS;

    const int wWin = blockIdx.x;      // 0..127
    const int h    = blockIdx.y;      // 0..15
    const int b    = blockIdx.z;      // 0..3
    const int tid  = threadIdx.x;
    const int base = ((b * 16 + h) * 8192 + wWin * 64) * 64;  // < 2^31

    // ---- cooperative tile load: 64x64 floats each, fully contiguous ----
    {
        const float4* qsrc = reinterpret_cast<const float4*>(Q + base);
        const float4* ksrc = reinterpret_cast<const float4*>(K + base);
        const float4* vsrc = reinterpret_cast<const float4*>(V + base);
#pragma unroll
        for (int it = 0; it < 4; it++) {
            int idx = tid + it * 256;            // 0..1023 float4s
            int row = idx >> 4;
            int col = (idx & 15) << 2;
            int so  = row * STRIDE + col;
            *reinterpret_cast<float4*>(qs + so) = qsrc[idx];
            *reinterpret_cast<float4*>(ks + so) = ksrc[idx];
            *reinterpret_cast<float4*>(vs + so) = vsrc[idx];
        }
    }
    __syncthreads();

    const int w_id = tid >> 5;
    const int lane = tid & 31;

    float acc[16];
#pragma unroll
    for (int j = 0; j < 16; j++) acc[j] = 0.f;

    // ---- rate 1 (S=8): always 1 segment per warp, active by head parity ----
    if ((w_id & 1) == (h & 1))
        seg_attn<2>(qs, ks, vs, ps, w_id, lane, w_id << 3, acc);

    // ---- rate 2 (S=16) ----
    if ((w_id >> 1) == (h & 3)) {
        int k0 = (w_id >> 1) << 4;
        if (w_id & 1) seg_attn<4>(qs, ks, vs, ps, w_id, lane, k0, acc);
        else          seg_attn<2>(qs, ks, vs, ps, w_id, lane, k0, acc);
    }

    // ---- rate 3 (S=32) ----
    {
        int j3 = w_id >> 2;
        if ((((wWin << 1) + j3) & 7) == (h & 7)) {
            int k0 = j3 << 5;
            switch (w_id & 3) {
                case 0: seg_attn<2>(qs, ks, vs, ps, w_id, lane, k0, acc); break;
                case 1: seg_attn<4>(qs, ks, vs, ps, w_id, lane, k0, acc); break;
                case 2: seg_attn<6>(qs, ks, vs, ps, w_id, lane, k0, acc); break;
                case 3: seg_attn<8>(qs, ks, vs, ps, w_id, lane, k0, acc); break;
            }
        }
    }

    // ---- rate 4 (S=64) ----
    if ((wWin & 15) == (h & 15)) {
        switch (w_id) {
            case 0: seg_attn<2>(qs, ks, vs, ps, w_id, lane, 0, acc); break;
            case 1: seg_attn<4>(qs, ks, vs, ps, w_id, lane, 0, acc); break;
            case 2: seg_attn<6>(qs, ks, vs, ps, w_id, lane, 0, acc); break;
            case 3: seg_attn<8>(qs, ks, vs, ps, w_id, lane, 0, acc); break;
            case 4: seg_attn<10>(qs, ks, vs, ps, w_id, lane, 0, acc); break;
            case 5: seg_attn<12>(qs, ks, vs, ps, w_id, lane, 0, acc); break;
            case 6: seg_attn<14>(qs, ks, vs, ps, w_id, lane, 0, acc); break;
            case 7: seg_attn<16>(qs, ks, vs, ps, w_id, lane, 0, acc); break;
        }
    }

    // ---- write (avg over the 4 rates); every row written, zeros included ----
    const int i  = lane >> 2;
    const int kk = lane & 3;
    const int qr = (w_id << 3) + i;
    float* orow = out + base + qr * 64 + (kk << 4);
#pragma unroll
    for (int j = 0; j < 4; j++) {
        float4 o;
        o.x = acc[j * 4 + 0] * 0.25f;
        o.y = acc[j * 4 + 1] * 0.25f;
        o.z = acc[j * 4 + 2] * 0.25f;
        o.w = acc[j * 4 + 3] * 0.25f;
        *reinterpret_cast<float4*>(orow + j * 4) = o;
    }
}

extern "C" void kernel_launch(void* const* d_in, const int* in_sizes, int n_in,
                              void* d_out, int out_size)
{
    const float* Q = (const float*)d_in[0];
    const float* K = (const float*)d_in[1];
    const float* V = (const float*)d_in[2];
    float* out = (float*)d_out;

    // >48KB dynamic smem requires opt-in; idempotent, not a stream op.
    cudaFuncSetAttribute(dilated_attn_kernel,
                         cudaFuncAttributeMaxDynamicSharedMemorySize, SMEM_BYTES);

    dim3 grid(128, 16, 4);
    dilated_attn_kernel<<<grid, 256, SMEM_BYTES>>>(Q, K, V, out);
}

// round 3
// speedup vs baseline: 1.1672x; 1.1672x over previous
#include <cuda_runtime.h>

// Dilated attention, fused over all 4 rates.
// B=4, H=16, T=8192, D=64. One block per (b, h, 64-token window).
//   r=1: S=8,  warp j active iff j%2==h%2,              k0=8j
//   r=2: S=16, seg j2=wid>>1 active iff j2==h%4,        k0=16*j2
//   r=3: S=32, seg j3=wid>>2 active iff (2w+j3)%8==h%8, k0=32*j3
//   r=4: S=64, active iff w%16==h%16,                   k0=0
// Each warp owns 8 query rows. Lane: i=lane>>2 (row), kk=lane&3 (key slot /
// d-quarter). Probs stay in registers; PV broadcasts them via shfl.

#define STRIDE 68   // smem row stride (floats), conflict-free

__device__ __forceinline__ float dot4(float4 a, float4 b) {
    return a.x * b.x + a.y * b.y + a.z * b.z + a.w * b.w;
}

__device__ __forceinline__ void cp16(unsigned int saddr, const float* g) {
    asm volatile("cp.async.cg.shared.global [%0], [%1], 16;\n"
                 :: "r"(saddr), "l"(g));
}

template <int NB>
__device__ __forceinline__ void seg_attn(
    const float* __restrict__ qs, const float* __restrict__ ks,
    const float* __restrict__ vs, int w_id, int lane, int k0, float* acc)
{
    const int i  = lane >> 2;
    const int kk = lane & 3;
    const int qr = (w_id << 3) + i;
    const float* qrow  = qs + qr * STRIDE;
    const float* kbase = ks + (k0 + kk) * STRIDE;

    // scores: lane computes NB dots (keys k0+kk, k0+kk+4, ...)
    float sc[NB];
#pragma unroll
    for (int kb = 0; kb < NB; kb++) sc[kb] = 0.f;
#pragma unroll 4
    for (int dc = 0; dc < 16; dc++) {
        float4 qv = *reinterpret_cast<const float4*>(qrow + dc * 4);
#pragma unroll
        for (int kb = 0; kb < NB; kb++) {
            float4 kv = *reinterpret_cast<const float4*>(kbase + kb * 4 * STRIDE + dc * 4);
            sc[kb] += dot4(qv, kv);
        }
    }

    // causal mask + scale + softmax (4-lane groups share a row)
    float m = -1e30f;
#pragma unroll
    for (int kb = 0; kb < NB; kb++) {
        int key = k0 + kb * 4 + kk;
        sc[kb] = (key <= qr) ? sc[kb] * 0.125f : -1e30f;
        m = fmaxf(m, sc[kb]);
    }
    m = fmaxf(m, __shfl_xor_sync(0xffffffffu, m, 1));
    m = fmaxf(m, __shfl_xor_sync(0xffffffffu, m, 2));
    float sum = 0.f;
#pragma unroll
    for (int kb = 0; kb < NB; kb++) { sc[kb] = __expf(sc[kb] - m); sum += sc[kb]; }
    sum += __shfl_xor_sync(0xffffffffu, sum, 1);
    sum += __shfl_xor_sync(0xffffffffu, sum, 2);
    float inv = 1.f / sum;
#pragma unroll
    for (int kb = 0; kb < NB; kb++) sc[kb] *= inv;

    // PV: lane accumulates its d-quarter; prob for key c comes from lane
    // (i*4 + (c&3)) register sc[c>>2] via shfl (static index after unroll).
    const int dq = kk << 4;
    const int srcbase = lane & ~3;
    const float* vbase = vs + k0 * STRIDE + dq;
#pragma unroll 4
    for (int c = 0; c < NB * 4; c++) {
        float p = __shfl_sync(0xffffffffu, sc[c >> 2], srcbase | (c & 3));
        const float* vr = vbase + c * STRIDE;
#pragma unroll
        for (int j = 0; j < 4; j++) {
            float4 vv = *reinterpret_cast<const float4*>(vr + j * 4);
            acc[j * 4 + 0] += p * vv.x;
            acc[j * 4 + 1] += p * vv.y;
            acc[j * 4 + 2] += p * vv.z;
            acc[j * 4 + 3] += p * vv.w;
        }
    }
}

#define SMEM_KS (64 * STRIDE)
#define SMEM_VS (2 * 64 * STRIDE)
#define SMEM_FLOATS (3 * 64 * STRIDE)
#define SMEM_BYTES  (SMEM_FLOATS * 4)

__global__ void __launch_bounds__(256, 4)
dilated_attn_kernel(const float* __restrict__ Q, const float* __restrict__ K,
                    const float* __restrict__ V, float* __restrict__ out)
{
    extern __shared__ float smem[];
    float* qs = smem;
    float* ks = smem + SMEM_KS;
    float* vs = smem + SMEM_VS;

    const int wWin = blockIdx.x;
    const int h    = blockIdx.y;
    const int b    = blockIdx.z;
    const int tid  = threadIdx.x;
    const int base = ((b * 16 + h) * 8192 + wWin * 64) * 64;

    const bool r4_act = ((wWin & 15) == (h & 15));

    // cooperative tile load via cp.async.cg (L1-bypass), skipping rows no
    // rate will ever touch for this (h, window). Q/K/V share the predicate.
    {
        unsigned int qa = (unsigned int)__cvta_generic_to_shared(qs);
        unsigned int ka = (unsigned int)__cvta_generic_to_shared(ks);
        unsigned int va = (unsigned int)__cvta_generic_to_shared(vs);
#pragma unroll
        for (int it = 0; it < 4; it++) {
            int idx = tid + it * 256;          // 0..1023 float4s
            int row = idx >> 4;
            int col = (idx & 15) << 2;
            bool need = (((row >> 3) & 1) == (h & 1))
                     || ((row >> 4) == (h & 3))
                     || ((((wWin << 1) + (row >> 5)) & 7) == (h & 7))
                     || r4_act;
            if (need) {
                unsigned int so = (unsigned int)(row * STRIDE + col) * 4u;
                int go = base + row * 64 + col;
                cp16(qa + so, Q + go);
                cp16(ka + so, K + go);
                cp16(va + so, V + go);
            }
        }
        asm volatile("cp.async.commit_group;\n");
        asm volatile("cp.async.wait_group 0;\n");
    }
    __syncthreads();

    const int w_id = tid >> 5;
    const int lane = tid & 31;

    float acc[16];
#pragma unroll
    for (int j = 0; j < 16; j++) acc[j] = 0.f;

    // rate 1 (S=8)
    if ((w_id & 1) == (h & 1))
        seg_attn<2>(qs, ks, vs, w_id, lane, w_id << 3, acc);

    // rate 2 (S=16)
    if ((w_id >> 1) == (h & 3)) {
        int k0 = (w_id >> 1) << 4;
        if (w_id & 1) seg_attn<4>(qs, ks, vs, w_id, lane, k0, acc);
        else          seg_attn<2>(qs, ks, vs, w_id, lane, k0, acc);
    }

    // rate 3 (S=32)
    {
        int j3 = w_id >> 2;
        if ((((wWin << 1) + j3) & 7) == (h & 7)) {
            int k0 = j3 << 5;
            switch (w_id & 3) {
                case 0: seg_attn<2>(qs, ks, vs, w_id, lane, k0, acc); break;
                case 1: seg_attn<4>(qs, ks, vs, w_id, lane, k0, acc); break;
                case 2: seg_attn<6>(qs, ks, vs, w_id, lane, k0, acc); break;
                case 3: seg_attn<8>(qs, ks, vs, w_id, lane, k0, acc); break;
            }
        }
    }

    // rate 4 (S=64)
    if (r4_act) {
        switch (w_id) {
            case 0: seg_attn<2>(qs, ks, vs, w_id, lane, 0, acc); break;
            case 1: seg_attn<4>(qs, ks, vs, w_id, lane, 0, acc); break;
            case 2: seg_attn<6>(qs, ks, vs, w_id, lane, 0, acc); break;
            case 3: seg_attn<8>(qs, ks, vs, w_id, lane, 0, acc); break;
            case 4: seg_attn<10>(qs, ks, vs, w_id, lane, 0, acc); break;
            case 5: seg_attn<12>(qs, ks, vs, w_id, lane, 0, acc); break;
            case 6: seg_attn<14>(qs, ks, vs, w_id, lane, 0, acc); break;
            case 7: seg_attn<16>(qs, ks, vs, w_id, lane, 0, acc); break;
        }
    }

    // write (avg over 4 rates); rows untouched by any rate emit zeros
    const int i  = lane >> 2;
    const int kk = lane & 3;
    const int qr = (w_id << 3) + i;
    float* orow = out + base + qr * 64 + (kk << 4);
#pragma unroll
    for (int j = 0; j < 4; j++) {
        float4 o;
        o.x = acc[j * 4 + 0] * 0.25f;
        o.y = acc[j * 4 + 1] * 0.25f;
        o.z = acc[j * 4 + 2] * 0.25f;
        o.w = acc[j * 4 + 3] * 0.25f;
        *reinterpret_cast<float4*>(orow + j * 4) = o;
    }
}

extern "C" void kernel_launch(void* const* d_in, const int* in_sizes, int n_in,
                              void* d_out, int out_size)
{
    const float* Q = (const float*)d_in[0];
    const float* K = (const float*)d_in[1];
    const float* V = (const float*)d_in[2];
    float* out = (float*)d_out;

    cudaFuncSetAttribute(dilated_attn_kernel,
                         cudaFuncAttributeMaxDynamicSharedMemorySize, SMEM_BYTES);

    dim3 grid(128, 16, 4);
    dilated_attn_kernel<<<grid, 256, SMEM_BYTES>>>(Q, K, V, out);
}

// round 4
// speedup vs baseline: 1.2051x; 1.0325x over previous
#include <cuda_runtime.h>

// Dilated attention, fused over all 4 rates.
// B=4, H=16, T=8192, D=64. One block (512 thr) per (b, h, 64-token window).
// 16 warps; warp t owns rows 4t..4t+3. Lane: i=lane>>3 (row), kk=lane&7
// (key slot AND d-eighth). Keys for lane: k0+8m+kk. Output: lane owns 8
// floats (d-eighth) of its row.
//   r1: S=8,  seg j1=t>>1, active iff j1%2==h%2,        k0=8*j1,  NBP 1
//   r2: S=16, seg j2=t>>2, active iff j2==h%4,          k0=16*j2, NBP 1-2
//   r3: S=32, seg j3=t>>3, active iff (2w+j3)%8==h%8,   k0=32*j3, NBP 1-4
//   r4: S=64, active iff w%16==h%16,                    k0=0,     NBP 1-8

#define STRIDE 68   // smem row stride (floats), conflict-free

__device__ __forceinline__ float dot4(float4 a, float4 b) {
    return a.x * b.x + a.y * b.y + a.z * b.z + a.w * b.w;
}

__device__ __forceinline__ void cp16(unsigned int saddr, const float* g) {
    asm volatile("cp.async.cg.shared.global [%0], [%1], 16;\n"
                 :: "r"(saddr), "l"(g));
}

// NBP key-blocks of 8 keys. Lane handles keys k0+8m+kk, m<NBP.
template <int NBP>
__device__ __forceinline__ void seg_attn(
    const float* __restrict__ qs, const float* __restrict__ ks,
    const float* __restrict__ vs, int w_id, int lane, int k0, float* acc)
{
    const int i  = lane >> 3;
    const int kk = lane & 7;
    const int qr = (w_id << 2) + i;
    const float* qrow  = qs + qr * STRIDE;
    const float* kbase = ks + (k0 + kk) * STRIDE;

    // scores
    float sc[NBP];
#pragma unroll
    for (int m = 0; m < NBP; m++) sc[m] = 0.f;
#pragma unroll 4
    for (int dc = 0; dc < 16; dc++) {
        float4 qv = *reinterpret_cast<const float4*>(qrow + dc * 4);
#pragma unroll
        for (int m = 0; m < NBP; m++) {
            float4 kv = *reinterpret_cast<const float4*>(kbase + m * 8 * STRIDE + dc * 4);
            sc[m] += dot4(qv, kv);
        }
    }

    // causal mask + scale + softmax (8-lane groups share a row)
    float mx = -1e30f;
#pragma unroll
    for (int m = 0; m < NBP; m++) {
        int key = k0 + m * 8 + kk;
        sc[m] = (key <= qr) ? sc[m] * 0.125f : -1e30f;
        mx = fmaxf(mx, sc[m]);
    }
    mx = fmaxf(mx, __shfl_xor_sync(0xffffffffu, mx, 1));
    mx = fmaxf(mx, __shfl_xor_sync(0xffffffffu, mx, 2));
    mx = fmaxf(mx, __shfl_xor_sync(0xffffffffu, mx, 4));
    float sum = 0.f;
#pragma unroll
    for (int m = 0; m < NBP; m++) { sc[m] = __expf(sc[m] - mx); sum += sc[m]; }
    sum += __shfl_xor_sync(0xffffffffu, sum, 1);
    sum += __shfl_xor_sync(0xffffffffu, sum, 2);
    sum += __shfl_xor_sync(0xffffffffu, sum, 4);
    float inv = 1.f / sum;
#pragma unroll
    for (int m = 0; m < NBP; m++) sc[m] *= inv;

    // PV: lane accumulates its d-eighth; prob for key c broadcast via shfl
    const int srcbase = lane & ~7;
    const float* vbase = vs + k0 * STRIDE + kk * 8;
#pragma unroll 4
    for (int c = 0; c < NBP * 8; c++) {
        float p = __shfl_sync(0xffffffffu, sc[c >> 3], srcbase | (c & 7));
        const float* vr = vbase + c * STRIDE;
        float4 v0 = *reinterpret_cast<const float4*>(vr);
        float4 v1 = *reinterpret_cast<const float4*>(vr + 4);
        acc[0] += p * v0.x; acc[1] += p * v0.y;
        acc[2] += p * v0.z; acc[3] += p * v0.w;
        acc[4] += p * v1.x; acc[5] += p * v1.y;
        acc[6] += p * v1.z; acc[7] += p * v1.w;
    }
}

#define SMEM_KS (64 * STRIDE)
#define SMEM_VS (2 * 64 * STRIDE)
#define SMEM_FLOATS (3 * 64 * STRIDE)
#define SMEM_BYTES  (SMEM_FLOATS * 4)

__global__ void __launch_bounds__(512, 3)
dilated_attn_kernel(const float* __restrict__ Q, const float* __restrict__ K,
                    const float* __restrict__ V, float* __restrict__ out)
{
    extern __shared__ float smem[];
    float* qs = smem;
    float* ks = smem + SMEM_KS;
    float* vs = smem + SMEM_VS;

    const int wWin = blockIdx.x;
    const int h    = blockIdx.y;
    const int b    = blockIdx.z;
    const int tid  = threadIdx.x;
    const int base = ((b * 16 + h) * 8192 + wWin * 64) * 64;

    const bool r4_act = ((wWin & 15) == (h & 15));

    // cooperative tile load via cp.async.cg, skipping never-touched rows
    {
        unsigned int qa = (unsigned int)__cvta_generic_to_shared(qs);
        unsigned int ka = (unsigned int)__cvta_generic_to_shared(ks);
        unsigned int va = (unsigned int)__cvta_generic_to_shared(vs);
#pragma unroll
        for (int it = 0; it < 2; it++) {
            int idx = tid + it * 512;          // 0..1023 float4s
            int row = idx >> 4;
            int col = (idx & 15) << 2;
            bool need = (((row >> 3) & 1) == (h & 1))
                     || ((row >> 4) == (h & 3))
                     || ((((wWin << 1) + (row >> 5)) & 7) == (h & 7))
                     || r4_act;
            if (need) {
                unsigned int so = (unsigned int)(row * STRIDE + col) * 4u;
                int go = base + row * 64 + col;
                cp16(qa + so, Q + go);
                cp16(ka + so, K + go);
                cp16(va + so, V + go);
            }
        }
        asm volatile("cp.async.commit_group;\n");
        asm volatile("cp.async.wait_group 0;\n");
    }
    __syncthreads();

    const int w_id = tid >> 5;   // 0..15
    const int lane = tid & 31;

    float acc[8];
#pragma unroll
    for (int j = 0; j < 8; j++) acc[j] = 0.f;

    // rate 1 (S=8): seg j1 = w_id>>1
    if (((w_id >> 1) & 1) == (h & 1))
        seg_attn<1>(qs, ks, vs, w_id, lane, (w_id >> 1) << 3, acc);

    // rate 2 (S=16): seg j2 = w_id>>2
    if ((w_id >> 2) == (h & 3)) {
        int k0 = (w_id >> 2) << 4;
        if ((w_id & 3) < 2) seg_attn<1>(qs, ks, vs, w_id, lane, k0, acc);
        else                seg_attn<2>(qs, ks, vs, w_id, lane, k0, acc);
    }

    // rate 3 (S=32): seg j3 = w_id>>3
    {
        int j3 = w_id >> 3;
        if ((((wWin << 1) + j3) & 7) == (h & 7)) {
            int k0 = j3 << 5;
            switch ((w_id & 7) >> 1) {
                case 0: seg_attn<1>(qs, ks, vs, w_id, lane, k0, acc); break;
                case 1: seg_attn<2>(qs, ks, vs, w_id, lane, k0, acc); break;
                case 2: seg_attn<3>(qs, ks, vs, w_id, lane, k0, acc); break;
                case 3: seg_attn<4>(qs, ks, vs, w_id, lane, k0, acc); break;
            }
        }
    }

    // rate 4 (S=64)
    if (r4_act) {
        switch (w_id >> 1) {
            case 0: seg_attn<1>(qs, ks, vs, w_id, lane, 0, acc); break;
            case 1: seg_attn<2>(qs, ks, vs, w_id, lane, 0, acc); break;
            case 2: seg_attn<3>(qs, ks, vs, w_id, lane, 0, acc); break;
            case 3: seg_attn<4>(qs, ks, vs, w_id, lane, 0, acc); break;
            case 4: seg_attn<5>(qs, ks, vs, w_id, lane, 0, acc); break;
            case 5: seg_attn<6>(qs, ks, vs, w_id, lane, 0, acc); break;
            case 6: seg_attn<7>(qs, ks, vs, w_id, lane, 0, acc); break;
            case 7: seg_attn<8>(qs, ks, vs, w_id, lane, 0, acc); break;
        }
    }

    // write (avg over 4 rates); untouched rows emit zeros
    const int i  = lane >> 3;
    const int kk = lane & 7;
    const int qr = (w_id << 2) + i;
    float* orow = out + base + qr * 64 + kk * 8;
    float4 o0, o1;
    o0.x = acc[0] * 0.25f; o0.y = acc[1] * 0.25f;
    o0.z = acc[2] * 0.25f; o0.w = acc[3] * 0.25f;
    o1.x = acc[4] * 0.25f; o1.y = acc[5] * 0.25f;
    o1.z = acc[6] * 0.25f; o1.w = acc[7] * 0.25f;
    *reinterpret_cast<float4*>(orow)     = o0;
    *reinterpret_cast<float4*>(orow + 4) = o1;
}

extern "C" void kernel_launch(void* const* d_in, const int* in_sizes, int n_in,
                              void* d_out, int out_size)
{
    const float* Q = (const float*)d_in[0];
    const float* K = (const float*)d_in[1];
    const float* V = (const float*)d_in[2];
    float* out = (float*)d_out;

    cudaFuncSetAttribute(dilated_attn_kernel,
                         cudaFuncAttributeMaxDynamicSharedMemorySize, SMEM_BYTES);

    dim3 grid(128, 16, 4);
    dilated_attn_kernel<<<grid, 512, SMEM_BYTES>>>(Q, K, V, out);
}